// round 1
// baseline (speedup 1.0000x reference)
#include <cuda_runtime.h>
#include <math.h>

// Problem constants
#define NUM_INITS   64
#define BATCH_N     128
#define TOTAL_P     18378
// param offsets (flat): w1[16,1,5,5]=400 | b1[16] | w2[32,16,5,5]=12800 | b2[32] | wd[10,512] | bd[10]
#define OFF_W1      0
#define OFF_B1      400
#define OFF_W2      416
#define OFF_B2      13216
#define OFF_WD      13248
#define OFF_BD      18368

__global__ __launch_bounds__(256)
void ensemble_lenet_kernel(const float* __restrict__ params,
                           const float* __restrict__ batch,
                           float* __restrict__ out)
{
    __shared__ __align__(16) float s_img[784];     // 28x28
    __shared__ float s_w1[400];
    __shared__ float s_b1[16];
    __shared__ __align__(16) float s_a1[16 * 144]; // pooled conv1: 16 x 12 x 12
    __shared__ float s_w2[32 * 8 * 25];            // conv2 weight chunk (8 input chans)
    __shared__ float s_b2[32];
    __shared__ float s_a2[512];                    // pooled conv2, flattened (c*16 + py*4 + px)
    __shared__ float s_dot[16];

    const int blk  = blockIdx.x;
    const int init = blk >> 7;       // / 128
    const int n    = blk & 127;
    const int t    = threadIdx.x;

    const float* __restrict__ P   = params + init * TOTAL_P;
    const float* __restrict__ img = batch + n * 784;

    // ---------- stage image + conv1 params ----------
    #pragma unroll
    for (int idx = t; idx < 784; idx += 256) s_img[idx] = img[idx];
    for (int idx = t; idx < 400; idx += 256) s_w1[idx]  = P[OFF_W1 + idx];
    if (t < 16) s_b1[t] = P[OFF_B1 + t];
    if (t < 32) s_b2[t] = P[OFF_B2 + t];
    __syncthreads();

    // ---------- conv1 (5x5, valid) + bias + relu + maxpool2x2 ----------
    // 16 output channels, pooled 12x12.  t -> co = t>>4, 16 threads cover 144
    // pooled positions in 9 strided steps.  Weights live in registers; each
    // pooled output computes its 2x2 pre-pool window from a 6x6 patch streamed
    // row-by-row (6 LDS -> up to 20 FMA per row).
    {
        const int co  = t >> 4;
        const int l16 = t & 15;
        float w1r[25];
        #pragma unroll
        for (int q = 0; q < 25; q++) w1r[q] = s_w1[co * 25 + q];
        const float b1 = s_b1[co];

        #pragma unroll
        for (int k = 0; k < 9; k++) {
            const int idx = l16 + (k << 4);         // 0..143
            const int py = idx / 12;
            const int px = idx - py * 12;
            const int iy = py * 2, ix = px * 2;

            float a00 = b1, a01 = b1, a10 = b1, a11 = b1;
            #pragma unroll
            for (int r = 0; r < 6; r++) {
                float row[6];
                const float* ip = s_img + (iy + r) * 28 + ix;
                #pragma unroll
                for (int c = 0; c < 6; c++) row[c] = ip[c];
                if (r < 5) {
                    #pragma unroll
                    for (int dx = 0; dx < 5; dx++) {
                        const float w = w1r[r * 5 + dx];
                        a00 = fmaf(row[dx],     w, a00);
                        a01 = fmaf(row[dx + 1], w, a01);
                    }
                }
                if (r >= 1) {
                    #pragma unroll
                    for (int dx = 0; dx < 5; dx++) {
                        const float w = w1r[(r - 1) * 5 + dx];
                        a10 = fmaf(row[dx],     w, a10);
                        a11 = fmaf(row[dx + 1], w, a11);
                    }
                }
            }
            float m = fmaxf(fmaxf(a00, a01), fmaxf(a10, a11));
            s_a1[co * 144 + idx] = fmaxf(m, 0.0f);   // relu(max) == max(relu)
        }
    }
    __syncthreads();

    // ---------- conv2 (5x5 over 16ch) + bias + relu + maxpool2x2 ----------
    // 32 output channels, conv out 8x8. t -> c2 = t>>3, row y = t&7; each
    // thread accumulates one full x-row of 8 outputs. Weights streamed through
    // smem in 2 chunks of 8 input channels. Activation rows loaded as float4.
    const int c2 = t >> 3;
    const int j  = t & 7;
    float acc[8];
    {
        const float b2 = s_b2[c2];
        #pragma unroll
        for (int x = 0; x < 8; x++) acc[x] = b2;
    }

    for (int cb = 0; cb < 2; cb++) {
        // load weight chunk: s_w2[c][cj][tap], ci = cb*8 + cj
        for (int idx = t; idx < 6400; idx += 256) {
            const int c   = idx / 200;
            const int rem = idx - c * 200;
            const int cj  = rem / 25;
            const int tap = rem - cj * 25;
            s_w2[idx] = P[OFF_W2 + (c * 16 + cb * 8 + cj) * 25 + tap];
        }
        __syncthreads();

        #pragma unroll
        for (int cj = 0; cj < 8; cj++) {
            const float* abase = s_a1 + (cb * 8 + cj) * 144;
            const float* wbase = s_w2 + (c2 * 8 + cj) * 25;
            #pragma unroll
            for (int dy = 0; dy < 5; dy++) {
                const float4* rp = (const float4*)(abase + (j + dy) * 12);
                const float4 v0 = rp[0], v1 = rp[1], v2 = rp[2];
                float a[12];
                a[0]=v0.x; a[1]=v0.y; a[2]=v0.z; a[3]=v0.w;
                a[4]=v1.x; a[5]=v1.y; a[6]=v1.z; a[7]=v1.w;
                a[8]=v2.x; a[9]=v2.y; a[10]=v2.z; a[11]=v2.w;
                #pragma unroll
                for (int dx = 0; dx < 5; dx++) {
                    const float w = wbase[dy * 5 + dx];
                    #pragma unroll
                    for (int x = 0; x < 8; x++)
                        acc[x] = fmaf(a[x + dx], w, acc[x]);
                }
            }
        }
        __syncthreads();
    }

    // pool rows pairwise via shuffle (t and t^1 are rows y and y^1, same c2)
    {
        float m[8];
        #pragma unroll
        for (int x = 0; x < 8; x++) {
            const float other = __shfl_xor_sync(0xFFFFFFFFu, acc[x], 1);
            m[x] = fmaxf(acc[x], other);
        }
        if ((j & 1) == 0) {
            const int py = j >> 1;
            #pragma unroll
            for (int px = 0; px < 4; px++) {
                const float v = fmaxf(fmaxf(m[2 * px], m[2 * px + 1]), 0.0f);
                s_a2[c2 * 16 + py * 4 + px] = v;
            }
        }
    }
    __syncthreads();

    // ---------- dense 512 -> 10 ----------
    // 10 outputs x 16 lanes each (t < 160); weights straight from L2 (hot).
    {
        const int o = t >> 4;
        if (o < 10) {
            const int l = t & 15;
            const float* wrow = P + OFF_WD + o * 512;
            float partial = 0.0f;
            #pragma unroll 8
            for (int f = l; f < 512; f += 16)
                partial = fmaf(wrow[f], s_a2[f], partial);
            #pragma unroll
            for (int off = 8; off; off >>= 1)
                partial += __shfl_down_sync(0xFFFFFFFFu, partial, off, 16);
            if (l == 0) s_dot[o] = partial + P[OFF_BD + o];
        }
    }
    __syncthreads();

    // ---------- log_softmax over 10, write out ----------
    if (t < 32) {
        const float v = (t < 10) ? s_dot[t] : -INFINITY;
        float mx = v;
        #pragma unroll
        for (int off = 16; off; off >>= 1)
            mx = fmaxf(mx, __shfl_xor_sync(0xFFFFFFFFu, mx, off));
        float e = (t < 10) ? __expf(v - mx) : 0.0f;
        float s = e;
        #pragma unroll
        for (int off = 16; off; off >>= 1)
            s += __shfl_xor_sync(0xFFFFFFFFu, s, off);
        if (t < 10)
            out[(init * BATCH_N + n) * 10 + t] = v - mx - __logf(s);
    }
}

extern "C" void kernel_launch(void* const* d_in, const int* in_sizes, int n_in,
                              void* d_out, int out_size)
{
    const float* params = (const float*)d_in[0];
    const float* batch  = (const float*)d_in[1];
    // defensive: identify inputs by size
    if (n_in >= 2 && in_sizes[0] != NUM_INITS * TOTAL_P) {
        params = (const float*)d_in[1];
        batch  = (const float*)d_in[0];
    }
    float* out = (float*)d_out;
    ensemble_lenet_kernel<<<NUM_INITS * BATCH_N, 256>>>(params, batch, out);
}